// round 12
// baseline (speedup 1.0000x reference)
#include <cuda_runtime.h>

// AutoregressiveBisectionInverter — closed-form inversion, R12.
//
// W strictly lower triangular => bisected function is linear in x_i:
//   x_i = (y_i - sum_{j<i} W[i,j] tanh(x_j)) / softplus(a_i)
//
// R12: UNSCALED accumulators. Stage -W raw (no softplus dependency, single
// barrier); acc = y - sum W t; softplus inverses applied (a) to diag-band
// weights per chunk (off-chain muls), (b) to shfl sources (lane pre-scales
// its own acc), (c) to the final store. Chain unchanged: 64x (FMA+MUFU.TANH).
//
// One warp per batch row; lane l accumulates dims {l, l+32}. W[l][j]=0 for
// j>=l => lane l's accumulator FREEZES once column l passes; acc0 (dims
// 0..31) is stored at mid-loop so the STG drain overlaps chunks 8..15.

#define AD 64
#define AB 512
#define ROWS_PER_BLOCK 4
#define NTHREADS (32 * ROWS_PER_BLOCK)
#define WSTRIDE 68

__device__ __forceinline__ float tanh_fast(float x) {
    float r;
    asm("tanh.approx.f32 %0, %1;" : "=f"(r) : "f"(x));
    return r;
}

__device__ __forceinline__ float inv_softplus(float x) {
    // 1 / log(1 + e^x), MUFU-only; x in [0.5, 1.5].
    return __fdividef(1.0f, __logf(1.0f + __expf(x)));
}

__global__ __launch_bounds__(NTHREADS, 1)
void arbi_kernel(const float* __restrict__ y,
                 const float* __restrict__ a,
                 const float* __restrict__ W,
                 float* __restrict__ out)
{
    __shared__ float invs_sh[AD];
    __shared__ __align__(16) float Wsh[AD * WSTRIDE];   // holds -W (raw, negated)

    const int tid  = threadIdx.x;
    const int lane = tid & 31;
    const int warp = tid >> 5;
    const int row  = blockIdx.x * ROWS_PER_BLOCK + warp;

    // ---- Issue ALL independent global loads up front (one round trip) ----
    const float* yr = y + row * AD;
    const float yv0 = yr[lane];
    const float yv1 = yr[lane + 32];

    const float4* W4 = (const float4*)W;
    float4 wv[8];
    #pragma unroll
    for (int k = 0; k < 8; ++k) {
        wv[k] = W4[tid + NTHREADS * k];
    }

    float av = 0.0f;
    if (tid < AD) av = a[tid];

    // softplus inverses compute CONCURRENTLY with W staging (no dependency).
    if (tid < AD) {
        invs_sh[tid] = inv_softplus(av);
    }

    // ---- Stage -W raw (negation only; STS issues as soon as LDG lands) ----
    #pragma unroll
    for (int k = 0; k < 8; ++k) {
        const int idx = tid + NTHREADS * k;  // float4 index; 16 per row
        const int r   = idx >> 4;
        const int c4  = idx & 15;
        float4 s;
        s.x = -wv[k].x; s.y = -wv[k].y; s.z = -wv[k].z; s.w = -wv[k].w;
        *(float4*)&Wsh[r * WSTRIDE + c4 * 4] = s;
    }
    __syncthreads();   // single barrier: covers invs_sh and Wsh

    // Per-lane inverse scales (broadcast-free LDS, off-chain).
    const float inv_l0 = invs_sh[lane];
    const float inv_l1 = invs_sh[lane + 32];

    // ---- Unscaled accumulators (double as outputs after final scale) ----
    float acc0 = yv0;
    float acc1 = yv1;

    // Chunk 0 partials in x-space: lane pre-scales its own acc, shfl picks owner.
    {
        const float src0 = acc0 * inv_l0;
        const float b0i = __shfl_sync(0xffffffffu, src0, 0);
        const float b1i = __shfl_sync(0xffffffffu, src0, 1);
        const float b2i = __shfl_sync(0xffffffffu, src0, 2);
        const float b3i = __shfl_sync(0xffffffffu, src0, 3);
        // fallthrough into loop via variables:
        float b0 = b0i, b1 = b1i, b2 = b2i, b3 = b3i;

        #pragma unroll
        for (int c = 0; c < 16; ++c) {
            const int j = 4 * c;

            // Row inverse scales for this chunk's diag band (lane-uniform).
            const float i1 = invs_sh[j + 1];
            const float i2 = invs_sh[j + 2];
            const float i3 = invs_sh[j + 3];

            // Raw (negated) diag-band weights; scale off-chain.
            const float  w10s   = Wsh[(j + 1) * WSTRIDE + j] * i1;
            const float2 w2r    = *(const float2*)&Wsh[(j + 2) * WSTRIDE + j];
            const float2 w3r    = *(const float2*)&Wsh[(j + 3) * WSTRIDE + j];
            const float  w32s   = Wsh[(j + 3) * WSTRIDE + j + 2] * i3;
            const float  w20s = w2r.x * i2, w21s = w2r.y * i2;
            const float  w30s = w3r.x * i3, w31s = w3r.y * i3;

            float2 w4 = {0.f, 0.f}, w5 = {0.f, 0.f};
            float2 w6 = {0.f, 0.f}, w7 = {0.f, 0.f};
            float i4 = 0.f, i5 = 0.f, i6 = 0.f, i7 = 0.f;
            if (c < 15) {
                i4 = invs_sh[j + 4]; i5 = invs_sh[j + 5];
                i6 = invs_sh[j + 6]; i7 = invs_sh[j + 7];
                w4 = *(const float2*)&Wsh[(j + 4) * WSTRIDE + j + 2];
                w5 = *(const float2*)&Wsh[(j + 5) * WSTRIDE + j + 2];
                w6 = *(const float2*)&Wsh[(j + 6) * WSTRIDE + j + 2];
                w7 = *(const float2*)&Wsh[(j + 7) * WSTRIDE + j + 2];
            }
            // Per-lane acc-update weights (raw negated; unscaled acc space).
            const float4 wla = *(const float4*)&Wsh[lane * WSTRIDE + j];
            const float4 wlb = *(const float4*)&Wsh[(lane + 32) * WSTRIDE + j];

            // ---- dim j ----
            const float t0 = tanh_fast(b0);

            // ---- dim j+1 ----
            const float x1 = fmaf(w10s, t0, b1);
            const float t1 = tanh_fast(x1);

            acc0 = fmaf(wla.x, t0, acc0);
            acc1 = fmaf(wlb.x, t0, acc1);
            acc0 = fmaf(wla.y, t1, acc0);
            acc1 = fmaf(wlb.y, t1, acc1);

            // Early shfl of next chunk's partials (x-space via own-inv
            // pre-scale); missing t_{j+2}, t_{j+3} replayed below.
            float bp0 = 0.f, bp1 = 0.f, bp2 = 0.f, bp3 = 0.f;
            if (c < 15) {
                const float src = (j + 4 < 32) ? acc0 * inv_l0 : acc1 * inv_l1;
                bp0 = __shfl_sync(0xffffffffu, src, (j + 4) & 31);
                bp1 = __shfl_sync(0xffffffffu, src, (j + 5) & 31);
                bp2 = __shfl_sync(0xffffffffu, src, (j + 6) & 31);
                bp3 = __shfl_sync(0xffffffffu, src, (j + 7) & 31);
            }

            // ---- dim j+2 ----
            const float x2 = fmaf(w21s, t1, fmaf(w20s, t0, b2));
            const float t2 = tanh_fast(x2);

            acc0 = fmaf(wla.z, t2, acc0);
            acc1 = fmaf(wlb.z, t2, acc1);

            // ---- dim j+3 ----
            const float x3 = fmaf(w32s, t2,
                            fmaf(w31s, t1, fmaf(w30s, t0, b3)));
            const float t3 = tanh_fast(x3);

            acc0 = fmaf(wla.w, t3, acc0);
            acc1 = fmaf(wlb.w, t3, acc1);

            // Replay t_{j+2}, t_{j+3} into the early-shfl'd partials
            // (scaled weights, off-chain muls).
            if (c < 15) {
                b0 = fmaf(w4.y * i4, t3, fmaf(w4.x * i4, t2, bp0));
                b1 = fmaf(w5.y * i5, t3, fmaf(w5.x * i5, t2, bp1));
                b2 = fmaf(w6.y * i6, t3, fmaf(w6.x * i6, t2, bp2));
                b3 = fmaf(w7.y * i7, t3, fmaf(w7.x * i7, t2, bp3));
            }

            // After chunk 7 (cols 0..31 applied), acc0 is frozen for all
            // lanes -> store early; STG drain overlaps chunks 8..15.
            if (c == 7) {
                out[row * AD + lane] = acc0 * inv_l0;
            }
        }
    }

    // Dims 32..63 final after the last chunk.
    out[row * AD + lane + 32] = acc1 * inv_l1;
}

extern "C" void kernel_launch(void* const* d_in, const int* in_sizes, int n_in,
                              void* d_out, int out_size)
{
    const float* y = (const float*)d_in[0];   // (512, 64)
    const float* a = (const float*)d_in[1];   // (64,)
    const float* W = (const float*)d_in[2];   // (64, 64)
    float* out = (float*)d_out;               // (512, 64)

    arbi_kernel<<<AB / ROWS_PER_BLOCK, NTHREADS>>>(y, a, W, out);
}

// round 14
// speedup vs baseline: 1.0385x; 1.0385x over previous
#include <cuda_runtime.h>

// AutoregressiveBisectionInverter — closed-form inversion, R13.
// R11 body + warp-specialized split staging of W.
//
// W strictly lower triangular => bisected function is linear in x_i:
//   x_i = (y_i - sum_{j<i} W[i,j] tanh(x_j)) / softplus(a_i)
// Pre-scale Wsh[i][j] = -W[i,j]/softplus(a_i), y'_i = y_i/softplus(a_i):
//   x_i = y'_i + sum_{j<i} Wsh[i,j] * tanh(x_j)
//
// One warp per batch row; lane l accumulates dims {l, l+32}. Wsh[l][j]=0 for
// j>=l => lane l's accumulator FREEZES at x_l; final acc IS the output; acc0
// (dims 0..31) stored at mid-loop so the STG drain overlaps chunks 8..15.
//
// R13: chunks 0..7 only touch W columns 0..31. Block = 160 threads: warps 0-3
// compute (stage only cols 0..31, 4 f4/thread), warp 4 stages cols 32..63 in
// the shadow of chunks 0..7. Producer/consumer named barrier (id 1, count
// 160): stager bar.arrive, compute bar.sync before chunk 8.

#define AD 64
#define AB 512
#define ROWS_PER_BLOCK 4
#define NCOMPUTE 128
#define NTHREADS 160
#define WSTRIDE 68

__device__ __forceinline__ float tanh_fast(float x) {
    float r;
    asm("tanh.approx.f32 %0, %1;" : "=f"(r) : "f"(x));
    return r;
}

__device__ __forceinline__ float inv_softplus(float x) {
    // 1 / log(1 + e^x), MUFU-only; x in [0.5, 1.5].
    return __fdividef(1.0f, __logf(1.0f + __expf(x)));
}

__global__ __launch_bounds__(NTHREADS, 1)
void arbi_kernel(const float* __restrict__ y,
                 const float* __restrict__ a,
                 const float* __restrict__ W,
                 float* __restrict__ out)
{
    __shared__ float invs_sh[AD];
    __shared__ __align__(16) float Wsh[AD * WSTRIDE];

    const int tid  = threadIdx.x;
    const int lane = tid & 31;
    const bool is_compute = (tid < NCOMPUTE);

    const float4* W4 = (const float4*)W;   // 16 float4 per row

    // ---- Phase 1: issue all independent LDGs, compute invs, one barrier ----
    float yv0 = 0.f, yv1 = 0.f;
    float4 wvc[4];                          // compute: first-half f4s
    float4 wvs[16];                         // stager: second-half f4s
    int row = 0;

    if (is_compute) {
        const int warp = tid >> 5;
        row = blockIdx.x * ROWS_PER_BLOCK + warp;
        const float* yr = y + row * AD;
        yv0 = yr[lane];
        yv1 = yr[lane + 32];
        #pragma unroll
        for (int k = 0; k < 4; ++k) {
            const int idx = tid + NCOMPUTE * k;      // 0..511
            const int r   = idx >> 3;                // row 0..63
            const int c4  = idx & 7;                 // f4-col 0..7 (cols 0..31)
            wvc[k] = W4[r * 16 + c4];
        }
    } else {
        const int s = tid - NCOMPUTE;                // stager lane 0..31
        #pragma unroll
        for (int k = 0; k < 16; ++k) {
            const int idx = s + 32 * k;              // 0..511
            const int r   = idx >> 3;
            const int c4  = 8 + (idx & 7);           // f4-col 8..15 (cols 32..63)
            wvs[k] = W4[r * 16 + c4];
        }
    }

    if (tid < AD) {
        invs_sh[tid] = inv_softplus(a[tid]);
    }
    __syncthreads();   // all 160: invs_sh visible; W LDGs in flight

    if (!is_compute) {
        // ---- Stager: scale + store second half, then arrive ----
        const int s = tid - NCOMPUTE;
        #pragma unroll
        for (int k = 0; k < 16; ++k) {
            const int idx = s + 32 * k;
            const int r   = idx >> 3;
            const int c4  = 8 + (idx & 7);
            const float sc = -invs_sh[r];
            float4 sv;
            sv.x = wvs[k].x * sc; sv.y = wvs[k].y * sc;
            sv.z = wvs[k].z * sc; sv.w = wvs[k].w * sc;
            *(float4*)&Wsh[r * WSTRIDE + c4 * 4] = sv;
        }
        asm volatile("bar.arrive 1, %0;" :: "n"(NTHREADS) : "memory");
        return;
    }

    // ---- Compute path ----
    const float inv_l0 = invs_sh[lane];
    const float inv_l1 = invs_sh[lane + 32];
    float acc0 = yv0 * inv_l0;
    float acc1 = yv1 * inv_l1;

    // Chunk-0 partials issued early; shfl latency overlaps the STS below.
    float b0 = __shfl_sync(0xffffffffu, acc0, 0);
    float b1 = __shfl_sync(0xffffffffu, acc0, 1);
    float b2 = __shfl_sync(0xffffffffu, acc0, 2);
    float b3 = __shfl_sync(0xffffffffu, acc0, 3);

    // Scale + store first half (4 f4/thread).
    #pragma unroll
    for (int k = 0; k < 4; ++k) {
        const int idx = tid + NCOMPUTE * k;
        const int r   = idx >> 3;
        const int c4  = idx & 7;
        const float sc = -invs_sh[r];
        float4 sv;
        sv.x = wvc[k].x * sc; sv.y = wvc[k].y * sc;
        sv.z = wvc[k].z * sc; sv.w = wvc[k].w * sc;
        *(float4*)&Wsh[r * WSTRIDE + c4 * 4] = sv;
    }
    // Compute-only barrier: first half of Wsh ready.
    asm volatile("bar.sync 2, %0;" :: "n"(NCOMPUTE) : "memory");

    #pragma unroll
    for (int c = 0; c < 16; ++c) {
        const int j = 4 * c;

        if (c == 8) {
            // Join with stager: second half of Wsh ready.
            asm volatile("bar.sync 1, %0;" :: "n"(NTHREADS) : "memory");
        }

        // Lane-uniform diag-band weights (broadcast LDS; pairs as v2).
        const float  w10    = Wsh[(j + 1) * WSTRIDE + j];
        const float2 w20_21 = *(const float2*)&Wsh[(j + 2) * WSTRIDE + j];
        const float2 w30_31 = *(const float2*)&Wsh[(j + 3) * WSTRIDE + j];
        const float  w32    = Wsh[(j + 3) * WSTRIDE + j + 2];
        float2 w4 = {0.f, 0.f}, w5 = {0.f, 0.f};
        float2 w6 = {0.f, 0.f}, w7 = {0.f, 0.f};
        if (c < 15) {
            w4 = *(const float2*)&Wsh[(j + 4) * WSTRIDE + j + 2];
            w5 = *(const float2*)&Wsh[(j + 5) * WSTRIDE + j + 2];
            w6 = *(const float2*)&Wsh[(j + 6) * WSTRIDE + j + 2];
            w7 = *(const float2*)&Wsh[(j + 7) * WSTRIDE + j + 2];
        }
        // Per-lane acc-update weights for this chunk's 4 columns (LDS.128).
        const float4 wla = *(const float4*)&Wsh[lane * WSTRIDE + j];
        const float4 wlb = *(const float4*)&Wsh[(lane + 32) * WSTRIDE + j];

        // ---- dim j ----
        const float t0 = tanh_fast(b0);

        // ---- dim j+1 ----
        const float x1 = fmaf(w10, t0, b1);
        const float t1 = tanh_fast(x1);

        acc0 = fmaf(wla.x, t0, acc0);
        acc1 = fmaf(wlb.x, t0, acc1);
        acc0 = fmaf(wla.y, t1, acc0);
        acc1 = fmaf(wlb.y, t1, acc1);

        // Early shfl of next chunk's partials (contain t_{<=j+1}); missing
        // t_{j+2}, t_{j+3} replayed below on all lanes.
        float bp0 = 0.f, bp1 = 0.f, bp2 = 0.f, bp3 = 0.f;
        if (c < 15) {
            const float src = (j + 4 < 32) ? acc0 : acc1;
            bp0 = __shfl_sync(0xffffffffu, src, (j + 4) & 31);
            bp1 = __shfl_sync(0xffffffffu, src, (j + 5) & 31);
            bp2 = __shfl_sync(0xffffffffu, src, (j + 6) & 31);
            bp3 = __shfl_sync(0xffffffffu, src, (j + 7) & 31);
        }

        // ---- dim j+2 ----
        const float x2 = fmaf(w20_21.y, t1, fmaf(w20_21.x, t0, b2));
        const float t2 = tanh_fast(x2);

        acc0 = fmaf(wla.z, t2, acc0);
        acc1 = fmaf(wlb.z, t2, acc1);

        // ---- dim j+3 ----
        const float x3 = fmaf(w32, t2,
                        fmaf(w30_31.y, t1, fmaf(w30_31.x, t0, b3)));
        const float t3 = tanh_fast(x3);

        acc0 = fmaf(wla.w, t3, acc0);
        acc1 = fmaf(wlb.w, t3, acc1);

        // Replay t_{j+2}, t_{j+3} into the early-shfl'd partials.
        if (c < 15) {
            b0 = fmaf(w4.y, t3, fmaf(w4.x, t2, bp0));
            b1 = fmaf(w5.y, t3, fmaf(w5.x, t2, bp1));
            b2 = fmaf(w6.y, t3, fmaf(w6.x, t2, bp2));
            b3 = fmaf(w7.y, t3, fmaf(w7.x, t2, bp3));
        }

        // After chunk 7 (cols 0..31 applied), acc0 is frozen for all lanes
        // -> store early; STG drain overlaps chunks 8..15.
        if (c == 7) {
            out[row * AD + lane] = acc0;
        }
    }

    // Dims 32..63 final after the last chunk.
    out[row * AD + lane + 32] = acc1;
}

extern "C" void kernel_launch(void* const* d_in, const int* in_sizes, int n_in,
                              void* d_out, int out_size)
{
    const float* y = (const float*)d_in[0];   // (512, 64)
    const float* a = (const float*)d_in[1];   // (64,)
    const float* W = (const float*)d_in[2];   // (64, 64)
    float* out = (float*)d_out;               // (512, 64)

    arbi_kernel<<<AB / ROWS_PER_BLOCK, NTHREADS>>>(y, a, W, out);
}